// round 1
// baseline (speedup 1.0000x reference)
#include <cuda_runtime.h>
#include <math_constants.h>

#define NPTS 3600
#define DD   128
#define HH   512
#define WW   512
#define NPB  900
#define HC   30
#define WC   30
#define SCOLS 3601   // 1 + NPTS

// ---------------- scratch (static device globals; no runtime allocation) ----
__device__ int   g_y1[NPTS], g_x1[NPTS];   // det1 sample: y1 = col(axis2 idx), x1 = row(axis3 idx)
__device__ int   g_yd[NPTS], g_xd[NPTS];   // det2 sample
__device__ int   g_xy2x[NPTS], g_xy2y[NPTS];
__device__ float g_A[NPTS * DD];           // s_des1
__device__ float g_B[NPTS * DD];           // distr

// offsets (i,j) with i^2+j^2 <= 4, lexicographic (i outer, j inner)
__constant__ int c_OI[13] = {-2,-1,-1,-1, 0, 0, 0, 0, 0, 1, 1, 1, 2};
__constant__ int c_OJ[13] = { 0,-1, 0, 1,-2,-1, 0, 1, 2,-1, 0, 1, 0};

// ---------------- kernel 1: per-cell argmax sample + descriptor gather ------
// grid.x = NPTS, grid.y = 2 (0 -> det1/des1, 1 -> det2/des2), 256 threads
__global__ void k_sample(const float* __restrict__ det1, const float* __restrict__ des1,
                         const float* __restrict__ det2, const float* __restrict__ des2)
{
    const int c = blockIdx.x;
    const int which = blockIdx.y;
    const float* det = which ? det2 : det1;
    const float* des = which ? des2 : des1;

    const int b = c / NPB, cell = c % NPB;
    const int hc = cell / WC, wc = cell % WC;
    const int t = threadIdx.x;
    const int i = t >> 4, j = t & 15;
    const int row = 16 + hc * 16 + i;
    const int col = 16 + wc * 16 + j;

    float v = det[((size_t)b * HH + row) * WW + col];

    __shared__ float sv[256];
    __shared__ int   si[256];
    sv[t] = v; si[t] = t;       // flattened cell index == t  (i*16+j)
    __syncthreads();
    for (int s = 128; s > 0; s >>= 1) {
        if (t < s) {
            float v2 = sv[t + s]; int i2 = si[t + s];
            if (v2 > sv[t] || (v2 == sv[t] && i2 < si[t])) { sv[t] = v2; si[t] = i2; }
        }
        __syncthreads();
    }
    const int best = si[0];
    const int bi = best >> 4, bj = best & 15;
    const int brow = 16 + hc * 16 + bi;   // "rows" -> used as axis3 index (x1 / xd)
    const int bcol = 16 + wc * 16 + bj;   // "cols" -> used as axis2 index (y1 / yd)

    if (t == 0) {
        if (which == 0) { g_y1[c] = bcol; g_x1[c] = brow; }
        else            { g_yd[c] = bcol; g_xd[c] = brow; }
    }
    if (t < DD) {
        float d = des[(((size_t)b * DD + t) * HH + bcol) * WW + brow];
        if (which == 0) g_A[(size_t)c * DD + t] = d;
        else            g_B[(size_t)c * DD + t] = d;
    }
}

// ---------------- kernel 2: neighbor matching (one warp per keypoint) -------
// grid = NPTS/4, 128 threads (4 warps)
__global__ void k_match(const float* __restrict__ des2, const float* __restrict__ aflow,
                        const float* __restrict__ qlt1, const float* __restrict__ qlt2,
                        float* __restrict__ out_scores, float* __restrict__ out_mask,
                        float* __restrict__ out_qlt)
{
    const int warp = threadIdx.x >> 5;
    const int lane = threadIdx.x & 31;
    const int n = blockIdx.x * 4 + warp;
    if (n >= NPTS) return;

    const int b  = n / NPB;
    const int y1 = g_y1[n];
    const int x1 = g_x1[n];

    // s_des1 row: 4 elems per lane (d = lane + 32*r)
    const float s0 = g_A[(size_t)n * DD + lane];
    const float s1 = g_A[(size_t)n * DD + lane + 32];
    const float s2 = g_A[(size_t)n * DD + lane + 64];
    const float s3 = g_A[(size_t)n * DD + lane + 96];

    const float ax = aflow[(((size_t)b * 2 + 0) * HH + y1) * WW + x1];
    const float ay = aflow[(((size_t)b * 2 + 1) * HH + y1) * WW + x1];
    const int xx = (int)(ax + 0.5f);   // trunc toward zero, matches astype(int32)
    const int yy = (int)(ay + 0.5f);
    const bool msk = (xx >= 0) && (yy >= 0) && (xx < WW) && (yy < HH);

    const float* db = des2 + (size_t)b * DD * HH * WW;
    const size_t plane = (size_t)HH * WW;

    float best = -CUDART_INF_F;
    int pos = 0;
    #pragma unroll
    for (int k = 0; k < 13; k++) {
        int px = xx + c_OI[k]; px = px < 0 ? 0 : (px > WW - 1 ? WW - 1 : px);
        int py = yy + c_OJ[k]; py = py < 0 ? 0 : (py > HH - 1 ? HH - 1 : py);
        const float* p = db + (size_t)py * WW + px;
        float dot = s0 * p[(size_t)lane * plane]
                  + s1 * p[(size_t)(lane + 32) * plane]
                  + s2 * p[(size_t)(lane + 64) * plane]
                  + s3 * p[(size_t)(lane + 96) * plane];
        #pragma unroll
        for (int off = 16; off > 0; off >>= 1)
            dot += __shfl_xor_sync(0xffffffffu, dot, off);
        if (dot > best) { best = dot; pos = k; }   // first-max (strict >, k ascending)
    }

    if (lane == 0) {
        int sx = xx + c_OI[pos]; sx = sx < 0 ? 0 : (sx > WW - 1 ? WW - 1 : sx);
        int sy = yy + c_OJ[pos]; sy = sy < 0 ? 0 : (sy > HH - 1 ? HH - 1 : sy);
        float q = 0.5f * (qlt1[((size_t)b * HH + y1) * WW + x1] +
                          qlt2[((size_t)b * HH + sy) * WW + sx]);
        out_scores[(size_t)n * SCOLS] = best;   // pscores -> column 0
        out_qlt[n]  = q;
        out_mask[n] = msk ? 1.0f : 0.0f;
        g_xy2x[n] = xx;
        g_xy2y[n] = yy;
    }
}

// ---------------- kernel 3: dscores GEMM (A @ B^T) + distance mask ---------
// 64x64 tile, 256 threads, 4x4 per thread, K chunked by 16
__global__ void k_gemm(float* __restrict__ out_scores)
{
    __shared__ float As[16][64];
    __shared__ float Bs[16][64];

    const int tid = threadIdx.x;
    const int tx = tid & 15, ty = tid >> 4;
    const int m0 = blockIdx.y * 64, n0 = blockIdx.x * 64;

    const int lr = tid >> 2;          // 0..63 row within tile
    const int lq = (tid & 3) * 4;     // k sub-offset 0,4,8,12

    float acc[4][4];
    #pragma unroll
    for (int u = 0; u < 4; u++)
        #pragma unroll
        for (int v = 0; v < 4; v++) acc[u][v] = 0.f;

    for (int kc = 0; kc < DD; kc += 16) {
        float4 av = make_float4(0.f, 0.f, 0.f, 0.f);
        float4 bv = make_float4(0.f, 0.f, 0.f, 0.f);
        if (m0 + lr < NPTS) av = *(const float4*)&g_A[(size_t)(m0 + lr) * DD + kc + lq];
        if (n0 + lr < NPTS) bv = *(const float4*)&g_B[(size_t)(n0 + lr) * DD + kc + lq];
        __syncthreads();
        As[lq + 0][lr] = av.x; As[lq + 1][lr] = av.y; As[lq + 2][lr] = av.z; As[lq + 3][lr] = av.w;
        Bs[lq + 0][lr] = bv.x; Bs[lq + 1][lr] = bv.y; Bs[lq + 2][lr] = bv.z; Bs[lq + 3][lr] = bv.w;
        __syncthreads();
        #pragma unroll
        for (int k = 0; k < 16; k++) {
            float4 a = *(const float4*)&As[k][ty * 4];
            float4 bb = *(const float4*)&Bs[k][tx * 4];
            float ar[4] = {a.x, a.y, a.z, a.w};
            float br[4] = {bb.x, bb.y, bb.z, bb.w};
            #pragma unroll
            for (int u = 0; u < 4; u++)
                #pragma unroll
                for (int v = 0; v < 4; v++) acc[u][v] = fmaf(ar[u], br[v], acc[u][v]);
        }
    }

    // epilogue: distance mask + write to scores[:, 1:]
    int rix[4], riy[4], rb[4], riv[4];
    int cjx[4], cjy[4], cb[4], cjv[4];
    #pragma unroll
    for (int u = 0; u < 4; u++) {
        int i = m0 + ty * 4 + u;
        riv[u] = (i < NPTS);
        int ii = riv[u] ? i : 0;
        rix[u] = g_xy2x[ii]; riy[u] = g_xy2y[ii]; rb[u] = ii / NPB;
    }
    #pragma unroll
    for (int v = 0; v < 4; v++) {
        int j = n0 + tx * 4 + v;
        cjv[v] = (j < NPTS);
        int jj = cjv[v] ? j : 0;
        cjx[v] = g_xd[jj]; cjy[v] = g_yd[jj]; cb[v] = jj / NPB;
    }
    #pragma unroll
    for (int u = 0; u < 4; u++) {
        if (!riv[u]) continue;
        const int i = m0 + ty * 4 + u;
        #pragma unroll
        for (int v = 0; v < 4; v++) {
            if (!cjv[v]) continue;
            const int j = n0 + tx * 4 + v;
            int dx = cjx[v] - rix[u];
            int dy = cjy[v] - riy[u];
            int dis2 = dx * dx + dy * dy + ((cb[v] != rb[u]) ? 4 : 0);
            float val = (dis2 < 4) ? 0.f : acc[u][v];
            out_scores[(size_t)i * SCOLS + 1 + j] = val;
        }
    }
}

// ---------------- kernel 4: labels (one-hot column 0) ----------------------
__global__ void k_labels(float* __restrict__ out_lab)
{
    const size_t row = blockIdx.x;
    for (int c = threadIdx.x; c < SCOLS; c += blockDim.x)
        out_lab[row * SCOLS + c] = (c == 0) ? 1.0f : 0.0f;
}

// ---------------- launch ----------------------------------------------------
extern "C" void kernel_launch(void* const* d_in, const int* in_sizes, int n_in,
                              void* d_out, int out_size)
{
    const float* des1  = (const float*)d_in[0];
    const float* det1  = (const float*)d_in[1];
    const float* qlt1  = (const float*)d_in[2];
    const float* des2  = (const float*)d_in[3];
    const float* det2  = (const float*)d_in[4];
    const float* qlt2  = (const float*)d_in[5];
    const float* aflow = (const float*)d_in[6];

    float* out        = (float*)d_out;
    float* out_scores = out;                                     // (3600, 3601)
    float* out_lab    = out + (size_t)NPTS * SCOLS;              // (3600, 3601)
    float* out_mask   = out_lab + (size_t)NPTS * SCOLS;          // (4, 900)
    float* out_qlt    = out_mask + NPTS;                         // (3600, 1)

    dim3 gs(NPTS, 2);
    k_sample<<<gs, 256>>>(det1, des1, det2, des2);

    k_match<<<NPTS / 4, 128>>>(des2, aflow, qlt1, qlt2, out_scores, out_mask, out_qlt);

    dim3 gg((NPTS + 63) / 64, (NPTS + 63) / 64);
    k_gemm<<<gg, 256>>>(out_scores);

    k_labels<<<NPTS, 256>>>(out_lab);
}